// round 1
// baseline (speedup 1.0000x reference)
#include <cuda_runtime.h>
#include <cstdint>

// Problem constants
#define NN 64
#define CC 32
#define MM 4000
#define LL 2000
#define DD 16
#define OO 32
#define KK (CC*DD)        // 512
#define CHUNK 128          // k per chunk (4 d-slices)
#define NCHUNK (KK/CHUNK)  // 4
#define LDA 132            // padded row stride (floats): 132 % 8 == 4 -> conflict-free LDS.128

// Scratch: transposed x, layout xT[m][n*32 + c], m-major.
__device__ float g_xT[(size_t)MM * NN * CC];

// ---------------------------------------------------------------------------
// Kernel 1: transpose x (2048 x 4000) -> xT (4000 x 2048)
// ---------------------------------------------------------------------------
__global__ void transpose_x_kernel(const float* __restrict__ x) {
    __shared__ float tile[32][33];
    int m0 = blockIdx.x * 32;          // column block in x (m)
    int r0 = blockIdx.y * 32;          // row block in x (nc)
    int tx = threadIdx.x, ty = threadIdx.y;   // (32, 8)
#pragma unroll
    for (int k = 0; k < 32; k += 8)
        tile[ty + k][tx] = x[(size_t)(r0 + ty + k) * MM + m0 + tx];
    __syncthreads();
#pragma unroll
    for (int k = 0; k < 32; k += 8)
        g_xT[(size_t)(m0 + ty + k) * (NN * CC) + r0 + tx] = tile[tx][ty + k];
}

// ---------------------------------------------------------------------------
// Kernel 2: per-l gather-GEMM.  out[n,o,l] = sum_k A[n,k]*B[o,k] + b[l,o]
//   k = d*32 + c.  A[n][k] = xT[idx[l,d]][n*32+c].  B[o][k] = W[l,o,c,d].
//   128 threads, 4n x 4o per thread, f32x2 packed FMA.
// ---------------------------------------------------------------------------
#define FMA2(c_, a_, b_) \
    asm("fma.rn.f32x2 %0, %1, %2, %3;" : "=l"(c_) : "l"(a_), "l"(b_), "l"(c_))

#define CP_ASYNC16(dst_, src_) \
    asm volatile("cp.async.cg.shared.global [%0], [%1], 16;" :: "r"(dst_), "l"(src_))

__global__ __launch_bounds__(128, 4)
void embed_bigraph_kernel(const float* __restrict__ W,
                          const float* __restrict__ bias,
                          const int*   __restrict__ idx,
                          float*       __restrict__ out) {
    extern __shared__ float sm[];
    float* As   = sm;                   // 64 x LDA
    float* Bs   = sm + 64 * LDA;        // 32 x LDA
    int*   idxs = (int*)(sm + 96 * LDA);

    const int l   = blockIdx.x;
    const int tid = threadIdx.x;
    const int nid = tid & 15;           // n = nid + 16*i
    const int oid = tid >> 4;           // o = oid + 8*j   (oid in [0,8))

    if (tid < DD) idxs[tid] = idx[l * DD + tid];

    const uint32_t as_base = (uint32_t)__cvta_generic_to_shared(As);

    unsigned long long acc[4][4];
#pragma unroll
    for (int i = 0; i < 4; i++)
#pragma unroll
        for (int j = 0; j < 4; j++) acc[i][j] = 0ull;   // (0.0f, 0.0f)

    for (int ch = 0; ch < NCHUNK; ch++) {
        __syncthreads();   // smem free to overwrite (also covers idxs on ch==0)

        // ---- A: 4 d-slices, each 2048 contiguous floats from xT, via cp.async
        // u in [0,2048) float4 units: dd = u/512, n = (u%512)/8, cg = (u%512)%8
#pragma unroll
        for (int t = 0; t < 16; t++) {
            int u  = tid + 128 * t;
            int dd = u >> 9;
            int v  = u & 511;
            int n  = v >> 3;
            int cg = v & 7;
            const float* src = g_xT + (size_t)idxs[ch * 4 + dd] * (NN * CC) + n * 32 + cg * 4;
            uint32_t dst = as_base + (uint32_t)(n * LDA + dd * 32 + cg * 4) * 4u;
            CP_ASYNC16(dst, src);
        }
        asm volatile("cp.async.commit_group;" ::: "memory");

        // ---- B: W[l] chunk (4 d per (o,c)) coalesced LDG.128, reordered STS
        float4 bst[8];
#pragma unroll
        for (int t = 0; t < 8; t++) {
            int p = tid + 128 * t;                       // p = o*32 + c
            bst[t] = *reinterpret_cast<const float4*>(
                W + ((size_t)l * 1024 + p) * DD + ch * 4);
        }
#pragma unroll
        for (int t = 0; t < 8; t++) {
            int p = tid + 128 * t;
            int o = p >> 5, c = p & 31;
            float* br = Bs + o * LDA + c;
            br[0]      = bst[t].x;
            br[32]     = bst[t].y;
            br[64]     = bst[t].z;
            br[96]     = bst[t].w;
        }

        asm volatile("cp.async.wait_group 0;" ::: "memory");
        __syncthreads();

        // ---- compute: 32 iterations of 4 k each
#pragma unroll 4
        for (int kk = 0; kk < CHUNK; kk += 4) {
            ulonglong2 a[4], b[4];
#pragma unroll
            for (int i = 0; i < 4; i++)
                a[i] = *reinterpret_cast<const ulonglong2*>(&As[(nid + 16 * i) * LDA + kk]);
#pragma unroll
            for (int j = 0; j < 4; j++)
                b[j] = *reinterpret_cast<const ulonglong2*>(&Bs[(oid + 8 * j) * LDA + kk]);
#pragma unroll
            for (int i = 0; i < 4; i++)
#pragma unroll
                for (int j = 0; j < 4; j++) {
                    FMA2(acc[i][j], a[i].x, b[j].x);
                    FMA2(acc[i][j], a[i].y, b[j].y);
                }
        }
    }

    // ---- epilogue: fold f32x2 halves, add bias, scattered store
#pragma unroll
    for (int j = 0; j < 4; j++) {
        int o = oid + 8 * j;
        float bj = __ldg(bias + l * OO + o);
#pragma unroll
        for (int i = 0; i < 4; i++) {
            int n = nid + 16 * i;
            unsigned int lo, hi;
            asm("mov.b64 {%0,%1}, %2;" : "=r"(lo), "=r"(hi) : "l"(acc[i][j]));
            float r = __uint_as_float(lo) + __uint_as_float(hi) + bj;
            out[(size_t)n * (OO * LL) + (size_t)o * LL + l] = r;
        }
    }
}

// ---------------------------------------------------------------------------
// Launch
// ---------------------------------------------------------------------------
extern "C" void kernel_launch(void* const* d_in, const int* in_sizes, int n_in,
                              void* d_out, int out_size) {
    const float* x    = (const float*)d_in[0];
    const float* W    = (const float*)d_in[1];
    const float* bias = (const float*)d_in[2];
    const int*   idx  = (const int*)d_in[3];
    float*       out  = (float*)d_out;

    const int smem_bytes = (96 * LDA + 16) * 4;   // As + Bs + idxs = 50752 B
    cudaFuncSetAttribute(embed_bigraph_kernel,
                         cudaFuncAttributeMaxDynamicSharedMemorySize, smem_bytes);

    transpose_x_kernel<<<dim3(MM / 32, (NN * CC) / 32), dim3(32, 8)>>>(x);
    embed_bigraph_kernel<<<LL, 128, smem_bytes>>>(W, bias, idx, out);
}